// round 3
// baseline (speedup 1.0000x reference)
#include <cuda_runtime.h>

#define BB   16
#define HH   64
#define LL   16384
#define NN   32
#define DCC  128
#define TT   512
#define NCHK 32
#define NSEQ (BB*HH)
#define NTOT (BB*HH*LL)

typedef unsigned long long u64;

__device__ float  g_buf0[NTOT];
__device__ float  g_buf1[NTOT];
__device__ float2 g_wre [HH*NN/2];
__device__ float2 g_wim [HH*NN/2];
__device__ float2 g_nwim[HH*NN/2];
__device__ float2 g_cre [HH*NN/2];
__device__ float2 g_cim [HH*NN/2];
__device__ float  g_wTre[HH*NN];
__device__ float  g_wTim[HH*NN];
__device__ float2 g_stre[NSEQ*NCHK*NN/2];
__device__ float2 g_stim[NSEQ*NCHK*NN/2];
__device__ float  g_gb  [BB*2*HH];
__device__ float  g_part[HH*BB*2];
__device__ float  g_mean[HH];
__device__ float  g_rstd[HH];

__device__ __forceinline__ u64 pk2(float lo, float hi) {
    u64 r; asm("mov.b64 %0, {%1, %2};" : "=l"(r) : "f"(lo), "f"(hi)); return r;
}
__device__ __forceinline__ void upk2(u64 v, float& lo, float& hi) {
    asm("mov.b64 {%0, %1}, %2;" : "=f"(lo), "=f"(hi) : "l"(v));
}
__device__ __forceinline__ u64 ffma2(u64 a, u64 b, u64 c) {
    u64 d; asm("fma.rn.f32x2 %0, %1, %2, %3;" : "=l"(d) : "l"(a), "l"(b), "l"(c)); return d;
}
__device__ __forceinline__ u64 fmul2(u64 a, u64 b) {
    u64 d; asm("mul.rn.f32x2 %0, %1, %2;" : "=l"(d) : "l"(a), "l"(b)); return d;
}

__global__ void prep_kernel(const float* __restrict__ log_dt, const float* __restrict__ log_A_real,
                            const float* __restrict__ A_imag, const float* __restrict__ C_re,
                            const float* __restrict__ C_im,  const float* __restrict__ cond,
                            const float* __restrict__ film_w, const float* __restrict__ film_b)
{
    int id = blockIdx.x*128 + threadIdx.x;
    if (id < HH*NN) {
        int h = id >> 5;
        double dt  = exp((double)log_dt[h]);
        double Are = -exp((double)log_A_real[id]);
        double Aim = (double)A_imag[id];
        double dre = Are*dt, dim = Aim*dt;
        double er  = exp(dre);
        double wre = er*cos(dim), wim = er*sin(dim);
        double e1r = wre - 1.0,   e1i = wim;
        double Cr = (double)C_re[id], Ci = (double)C_im[id];
        double numr = Cr*e1r - Ci*e1i;
        double numi = Cr*e1i + Ci*e1r;
        double den  = Are*Are + Aim*Aim;
        ((float*)g_wre )[id] = (float)wre;
        ((float*)g_wim )[id] = (float)wim;
        ((float*)g_nwim)[id] = (float)(-wim);
        ((float*)g_cre )[id] = (float)((numr*Are + numi*Aim)/den);
        ((float*)g_cim )[id] = (float)((numi*Are - numr*Aim)/den);
        double tr = dre*(double)TT, ti = dim*(double)TT;
        double et = exp(tr);
        g_wTre[id] = (float)(et*cos(ti));
        g_wTim[id] = (float)(et*sin(ti));
    } else if (id < HH*NN + BB*2*HH) {
        int j = id - HH*NN;
        int b = j >> 7, c = j & 127;
        double acc = (double)film_b[c];
        for (int d = 0; d < DCC; ++d)
            acc += (double)cond[b*DCC + d] * (double)film_w[c*DCC + d];
        g_gb[j] = (float)acc;
    }
}

template<int MODE>
__global__ void __launch_bounds__(256) gemm64_kernel(const float* __restrict__ xin,
        const float* __restrict__ W, const float* __restrict__ bias, const float* __restrict__ pa)
{
    __shared__ float ws[HH*HH];
    __shared__ float bs[HH];
    int tid = threadIdx.x;
    for (int i = tid; i < HH*HH; i += 256) { int g = i >> 6, h = i & 63; ws[h*HH + g] = W[i]; }
    if (tid < HH) bs[tid] = bias[tid];
    __syncthreads();

    const float* src = (MODE == 0) ? xin : g_buf1;
    int b = blockIdx.y;
    int p = blockIdx.x*256 + tid;
    size_t base = (size_t)b*HH*LL + p;

    float acc[HH];
    #pragma unroll
    for (int g = 0; g < HH; ++g) acc[g] = bs[g];

    #pragma unroll 4
    for (int h = 0; h < HH; ++h) {
        float xv = src[base + (size_t)h*LL];
        const float4* wr = reinterpret_cast<const float4*>(&ws[h*HH]);
        #pragma unroll
        for (int q = 0; q < 16; ++q) {
            float4 w4 = wr[q];
            acc[4*q+0] = fmaf(w4.x, xv, acc[4*q+0]);
            acc[4*q+1] = fmaf(w4.y, xv, acc[4*q+1]);
            acc[4*q+2] = fmaf(w4.z, xv, acc[4*q+2]);
            acc[4*q+3] = fmaf(w4.w, xv, acc[4*q+3]);
        }
    }
    float aa = (MODE == 0) ? pa[0] : 0.f;
    #pragma unroll
    for (int g = 0; g < HH; ++g) {
        float v = acc[g];
        if (MODE == 0) v = (v >= 0.f) ? v : aa*v;
        g_buf0[base + (size_t)g*LL - p + p + 0] = 0.f; /* placeholder removed below */
    }
    /* real store loop (kept separate so compiler vectorizes cleanly) */
    #pragma unroll
    for (int g = 0; g < HH; ++g) {
        float v = acc[g];
        if (MODE == 0) v = (v >= 0.f) ? v : aa*v;
        g_buf0[(size_t)b*HH*LL + (size_t)g*LL + p] = v;
    }
}

__global__ void __launch_bounds__(128) scanA_kernel()
{
    __shared__ float sh[64*33];
    int tid  = threadIdx.x;
    int ul   = tid >> 1, half = tid & 1;
    int u    = blockIdx.x*64 + ul;
    int bh   = u >> 5;
    int hch  = bh & 63;
    int pb   = hch*16 + half*8;

    const u64* wrp  = (const u64*)g_wre  + pb;
    const u64* wip  = (const u64*)g_wim  + pb;
    const u64* nwip = (const u64*)g_nwim + pb;
    u64 wre[8], wim[8], nwim[8], sre[8], sim[8];
    #pragma unroll
    for (int k = 0; k < 8; ++k) {
        wre[k] = wrp[k]; wim[k] = wip[k]; nwim[k] = nwip[k];
        sre[k] = 0ULL; sim[k] = 0ULL;
    }
    size_t gbase = (size_t)blockIdx.x * 64 * TT;

    for (int tile = 0; tile < TT/32; ++tile) {
        __syncthreads();
        #pragma unroll
        for (int it = 0; it < 16; ++it) {
            int idx = it*128 + tid;
            int uu = idx >> 5, lo = idx & 31;
            sh[uu*33 + lo] = g_buf0[gbase + (size_t)uu*TT + tile*32 + lo];
        }
        __syncthreads();
        #pragma unroll 4
        for (int l = 0; l < 32; ++l) {
            float hv = sh[ul*33 + l];
            u64 hh = pk2(hv, hv);
            #pragma unroll
            for (int k = 0; k < 8; ++k) {
                u64 t  = ffma2(nwim[k], sim[k], hh);
                u64 t2 = fmul2(wim[k],  sre[k]);
                sre[k] = ffma2(wre[k], sre[k], t);
                sim[k] = ffma2(wre[k], sim[k], t2);
            }
        }
    }
    int c = u & 31;
    int sb = (bh*NCHK + c)*16 + half*8;
    u64* pre = (u64*)g_stre; u64* pim = (u64*)g_stim;
    #pragma unroll
    for (int k = 0; k < 8; ++k) { pre[sb+k] = sre[k]; pim[sb+k] = sim[k]; }
}

__global__ void __launch_bounds__(128) scanB_kernel()
{
    int id  = blockIdx.x*128 + threadIdx.x;
    int bh  = id >> 5, n = id & 31;
    int hch = bh & 63;
    float wtr = g_wTre[hch*NN + n], wti = g_wTim[hch*NN + n];
    float Sre = 0.f, Sim = 0.f;
    float* pre = (float*)g_stre; float* pim = (float*)g_stim;
    for (int c = 0; c < NCHK; ++c) {
        int si = (bh*NCHK + c)*NN + n;
        float lre = pre[si], lim = pim[si];
        pre[si] = Sre; pim[si] = Sim;
        float nr = fmaf(wtr, Sre, fmaf(-wti, Sim, lre));
        float ni = fmaf(wtr, Sim, fmaf( wti, Sre, lim));
        Sre = nr; Sim = ni;
    }
}

__global__ void __launch_bounds__(128) scanC_kernel(const float* __restrict__ Dskip)
{
    __shared__ float sh [64*33];
    __shared__ float sho[64*33];
    int tid  = threadIdx.x;
    int ul   = tid >> 1, half = tid & 1;
    int u    = blockIdx.x*64 + ul;
    int bh   = u >> 5, c = u & 31;
    int hch  = bh & 63;
    int pb   = hch*16 + half*8;

    const u64* wrp  = (const u64*)g_wre  + pb;
    const u64* wip  = (const u64*)g_wim  + pb;
    const u64* nwip = (const u64*)g_nwim + pb;
    const u64* crp  = (const u64*)g_cre  + pb;
    const u64* cip  = (const u64*)g_cim  + pb;
    u64 wre[8], wim[8], nwim[8], cre[8], cim[8], sre[8], sim[8];
    int sb = (bh*NCHK + c)*16 + half*8;
    const u64* ire = (const u64*)g_stre; const u64* iim = (const u64*)g_stim;
    #pragma unroll
    for (int k = 0; k < 8; ++k) {
        wre[k] = wrp[k]; wim[k] = wip[k]; nwim[k] = nwip[k];
        cre[k] = crp[k]; cim[k] = cip[k];
        sre[k] = ire[sb+k]; sim[k] = iim[sb+k];
    }
    float dsk = Dskip[hch];
    size_t gbase = (size_t)blockIdx.x * 64 * TT;

    for (int tile = 0; tile < TT/32; ++tile) {
        __syncthreads();
        #pragma unroll
        for (int it = 0; it < 16; ++it) {
            int idx = it*128 + tid;
            int uu = idx >> 5, lo = idx & 31;
            sh[uu*33 + lo] = g_buf0[gbase + (size_t)uu*TT + tile*32 + lo];
        }
        __syncthreads();
        #pragma unroll 2
        for (int l = 0; l < 32; ++l) {
            float hv = sh[ul*33 + l];
            u64 hh = pk2(hv, hv);
            u64 ar = 0ULL, ai = 0ULL;
            #pragma unroll
            for (int k = 0; k < 8; ++k) {
                u64 t  = ffma2(nwim[k], sim[k], hh);
                u64 t2 = fmul2(wim[k],  sre[k]);
                sre[k] = ffma2(wre[k], sre[k], t);
                sim[k] = ffma2(wre[k], sim[k], t2);
                ar = ffma2(cre[k], sre[k], ar);
                ai = ffma2(cim[k], sim[k], ai);
            }
            float arl, arh, ail, aih;
            upk2(ar, arl, arh); upk2(ai, ail, aih);
            float p = (arl + arh) - (ail + aih);
            p += __shfl_xor_sync(0xffffffffu, p, 1);
            if (half == 0) sho[ul*33 + l] = fmaf(dsk, hv, 2.f*p);
        }
        __syncthreads();
        #pragma unroll
        for (int it = 0; it < 16; ++it) {
            int idx = it*128 + tid;
            int uu = idx >> 5, lo = idx & 31;
            g_buf1[gbase + (size_t)uu*TT + tile*32 + lo] = sho[uu*33 + lo];
        }
    }
}

__global__ void __launch_bounds__(256) stats_kernel()
{
    int b = blockIdx.x, g = blockIdx.y;
    const float4* p = (const float4*)(g_buf0 + ((size_t)b*HH + g)*LL);
    float s = 0.f, s2 = 0.f;
    for (int i = threadIdx.x; i < LL/4; i += 256) {
        float4 v = p[i];
        s  += v.x + v.y + v.z + v.w;
        s2 += v.x*v.x + v.y*v.y + v.z*v.z + v.w*v.w;
    }
    __shared__ float r1[256], r2[256];
    r1[threadIdx.x] = s; r2[threadIdx.x] = s2;
    __syncthreads();
    for (int o = 128; o > 0; o >>= 1) {
        if (threadIdx.x < o) { r1[threadIdx.x] += r1[threadIdx.x+o]; r2[threadIdx.x] += r2[threadIdx.x+o]; }
        __syncthreads();
    }
    if (threadIdx.x == 0) {
        g_part[(g*BB + b)*2    ] = r1[0];
        g_part[(g*BB + b)*2 + 1] = r2[0];
    }
}

__global__ void fin_kernel()
{
    int g = threadIdx.x;
    if (g >= HH) return;
    float s = 0.f, s2 = 0.f;
    for (int b = 0; b < BB; ++b) { s += g_part[(g*BB+b)*2]; s2 += g_part[(g*BB+b)*2 + 1]; }
    float inv = 1.f / (float)(BB*LL);
    float m   = s * inv;
    float var = fmaf(s2, inv, -m*m);
    g_mean[g] = m;
    g_rstd[g] = rsqrtf(var + 1e-5f);
}

__global__ void __launch_bounds__(256) final_kernel(const float* __restrict__ x,
        const float* __restrict__ res_w, const float* __restrict__ pa2, float* __restrict__ out)
{
    int idx = blockIdx.x*256 + threadIdx.x;
    int row = idx >> 12;
    int b = row >> 6, g = row & 63;
    float m  = g_mean[g], r = g_rstd[g];
    float ga = g_gb[b*2*HH + g], be = g_gb[b*2*HH + HH + g];
    float rw = res_w[g], aa = pa2[0];
    float4 y  = ((const float4*)g_buf0)[idx];
    float4 xv = ((const float4*)x)[idx];
    float4 o; float v;
    v = (y.x - m)*r; v = fmaf(ga, v, be); v = (v >= 0.f) ? v : aa*v; o.x = fmaf(rw, xv.x, v);
    v = (y.y - m)*r; v = fmaf(ga, v, be); v = (v >= 0.f) ? v : aa*v; o.y = fmaf(rw, xv.y, v);
    v = (y.z - m)*r; v = fmaf(ga, v, be); v = (v >= 0.f) ? v : aa*v; o.z = fmaf(rw, xv.z, v);
    v = (y.w - m)*r; v = fmaf(ga, v, be); v = (v >= 0.f) ? v : aa*v; o.w = fmaf(rw, xv.w, v);
    ((float4*)out)[idx] = o;
}

extern "C" void kernel_launch(void* const* d_in, const int* in_sizes, int n_in,
                              void* d_out, int out_size)
{
    const float* x        = (const float*)d_in[0];
    const float* cond     = (const float*)d_in[1];
    const float* linear_w = (const float*)d_in[2];
    const float* linear_b = (const float*)d_in[3];
    const float* prelu1_a = (const float*)d_in[4];
    const float* log_dt   = (const float*)d_in[5];
    const float* log_A_r  = (const float*)d_in[6];
    const float* A_imag   = (const float*)d_in[7];
    const float* C_re     = (const float*)d_in[8];
    const float* C_im     = (const float*)d_in[9];
    const float* Dskip    = (const float*)d_in[10];
    const float* out_w    = (const float*)d_in[11];
    const float* out_b    = (const float*)d_in[12];
    const float* film_w   = (const float*)d_in[13];
    const float* film_b   = (const float*)d_in[14];
    const float* prelu2_a = (const float*)d_in[15];
    const float* res_w    = (const float*)d_in[16];
    float* out = (float*)d_out;

    prep_kernel<<<32, 128>>>(log_dt, log_A_r, A_imag, C_re, C_im, cond, film_w, film_b);
    gemm64_kernel<0><<<dim3(LL/256, BB), 256>>>(x, linear_w, linear_b, prelu1_a);
    scanA_kernel<<<NSEQ*NCHK/64, 128>>>();
    scanB_kernel<<<NSEQ*NN/128, 128>>>();
    scanC_kernel<<<NSEQ*NCHK/64, 128>>>(Dskip);
    gemm64_kernel<1><<<dim3(LL/256, BB), 256>>>(x, out_w, out_b, prelu1_a);
    stats_kernel<<<dim3(BB, HH), 256>>>();
    fin_kernel<<<1, 64>>>();
    final_kernel<<<NTOT/4/256, 256>>>(x, res_w, prelu2_a, out);
}

// round 4
// speedup vs baseline: 1.0788x; 1.0788x over previous
#include <cuda_runtime.h>

#define BB   16
#define HH   64
#define LL   16384
#define NN   32
#define DCC  128
#define TT   512
#define NCHK 32
#define NSEQ (BB*HH)
#define NTOT (BB*HH*LL)

typedef unsigned long long u64;

__device__ float  g_buf0[NTOT];
__device__ float  g_buf1[NTOT];
__device__ float2 g_wre [HH*NN/2];
__device__ float2 g_wim [HH*NN/2];
__device__ float2 g_nwim[HH*NN/2];
__device__ float2 g_cre [HH*NN/2];
__device__ float2 g_cim [HH*NN/2];
__device__ float  g_wTre[HH*NN];
__device__ float  g_wTim[HH*NN];
__device__ float  g_stre[NSEQ*NCHK*NN];
__device__ float  g_stim[NSEQ*NCHK*NN];
__device__ float  g_gb  [BB*2*HH];
__device__ float  g_part[HH*BB*2];
__device__ float  g_mean[HH];
__device__ float  g_rstd[HH];

__device__ __forceinline__ u64 pk2(float lo, float hi) {
    u64 r; asm("mov.b64 %0, {%1, %2};" : "=l"(r) : "f"(lo), "f"(hi)); return r;
}
__device__ __forceinline__ void upk2(u64 v, float& lo, float& hi) {
    asm("mov.b64 {%0, %1}, %2;" : "=f"(lo), "=f"(hi) : "l"(v));
}
__device__ __forceinline__ u64 ffma2(u64 a, u64 b, u64 c) {
    u64 d; asm("fma.rn.f32x2 %0, %1, %2, %3;" : "=l"(d) : "l"(a), "l"(b), "l"(c)); return d;
}
__device__ __forceinline__ u64 fmul2(u64 a, u64 b) {
    u64 d; asm("mul.rn.f32x2 %0, %1, %2;" : "=l"(d) : "l"(a), "l"(b)); return d;
}

/* ---------------- prep: S4D derived params + FiLM GEMM ---------------- */
__global__ void prep_kernel(const float* __restrict__ log_dt, const float* __restrict__ log_A_real,
                            const float* __restrict__ A_imag, const float* __restrict__ C_re,
                            const float* __restrict__ C_im,  const float* __restrict__ cond,
                            const float* __restrict__ film_w, const float* __restrict__ film_b)
{
    int id = blockIdx.x*128 + threadIdx.x;
    if (id < HH*NN) {
        int h = id >> 5;
        double dt  = exp((double)log_dt[h]);
        double Are = -exp((double)log_A_real[id]);
        double Aim = (double)A_imag[id];
        double dre = Are*dt, dim = Aim*dt;
        double er  = exp(dre);
        double wre = er*cos(dim), wim = er*sin(dim);
        double e1r = wre - 1.0,   e1i = wim;
        double Cr = (double)C_re[id], Ci = (double)C_im[id];
        double numr = Cr*e1r - Ci*e1i;
        double numi = Cr*e1i + Ci*e1r;
        double den  = Are*Are + Aim*Aim;
        ((float*)g_wre )[id] = (float)wre;
        ((float*)g_wim )[id] = (float)wim;
        ((float*)g_nwim)[id] = (float)(-wim);
        ((float*)g_cre )[id] = (float)((numr*Are + numi*Aim)/den);
        ((float*)g_cim )[id] = (float)((numi*Are - numr*Aim)/den);
        double tr = dre*(double)TT, ti = dim*(double)TT;
        double et = exp(tr);
        g_wTre[id] = (float)(et*cos(ti));
        g_wTim[id] = (float)(et*sin(ti));
    } else if (id < HH*NN + BB*2*HH) {
        int j = id - HH*NN;
        int b = j >> 7, c = j & 127;
        double acc = (double)film_b[c];
        for (int d = 0; d < DCC; ++d)
            acc += (double)cond[b*DCC + d] * (double)film_w[c*DCC + d];
        g_gb[j] = (float)acc;
    }
}

/* ---------------- packed f32x2 64x64 channel GEMM ----------------
   MODE 0: x -> h with PReLU ; MODE 1: y1 -> y2.
   256 threads: tid<128 computes channels 0..31, tid>=128 channels 32..63.
   Each thread owns 2 adjacent positions packed in f32x2 lanes. */
template<int MODE>
__global__ void __launch_bounds__(256) gemm64p_kernel(const float* __restrict__ xin,
        const float* __restrict__ W, const float* __restrict__ bias, const float* __restrict__ pa)
{
    __shared__ u64 wp[HH*HH];     /* wp[h*64+g] = {W[g,h], W[g,h]} */
    int tid = threadIdx.x;
    for (int i = tid; i < HH*HH; i += 256) {
        int g = i >> 6, h = i & 63;
        float w = W[i];
        wp[h*HH + g] = pk2(w, w);
    }
    __syncthreads();

    const float* src = (MODE == 0) ? xin : g_buf1;
    int half  = tid >> 7;
    int tl    = tid & 127;
    int gbase = half * 32;
    int b     = blockIdx.y;
    int p2    = blockIdx.x*256 + tl*2;
    size_t sb = (size_t)b*HH*LL + p2;

    u64 acc[32];
    #pragma unroll
    for (int g = 0; g < 32; ++g) { float bv = bias[gbase+g]; acc[g] = pk2(bv, bv); }

    #pragma unroll 2
    for (int h = 0; h < HH; ++h) {
        float2 xv = *reinterpret_cast<const float2*>(&src[sb + (size_t)h*LL]);
        u64 xp = pk2(xv.x, xv.y);
        const ulonglong2* wrow = reinterpret_cast<const ulonglong2*>(&wp[h*HH + gbase]);
        #pragma unroll
        for (int q = 0; q < 16; ++q) {
            ulonglong2 w2 = wrow[q];
            acc[2*q  ] = ffma2(w2.x, xp, acc[2*q  ]);
            acc[2*q+1] = ffma2(w2.y, xp, acc[2*q+1]);
        }
    }
    float aa = (MODE == 0) ? pa[0] : 0.f;
    #pragma unroll
    for (int g = 0; g < 32; ++g) {
        float lo, hi; upk2(acc[g], lo, hi);
        if (MODE == 0) {
            lo = (lo >= 0.f) ? lo : aa*lo;
            hi = (hi >= 0.f) ? hi : aa*hi;
        }
        float2 o; o.x = lo; o.y = hi;
        *reinterpret_cast<float2*>(&g_buf0[(size_t)b*HH*LL + (size_t)(gbase+g)*LL + p2]) = o;
    }
}

/* ---------------- scanA: chunk-local states + fused inter-chunk prefix ----------------
   Block covers 2 sequences x 32 chunks. Unit ul=(bh_loc*32+c); 2 threads/unit. */
__global__ void __launch_bounds__(128) scanA_kernel()
{
    __shared__ float sh[64*33];
    __shared__ float st_re[2][NCHK][NN];
    __shared__ float st_im[2][NCHK][NN];
    int tid  = threadIdx.x;
    int ul   = tid >> 1, half = tid & 1;
    int u    = blockIdx.x*64 + ul;
    int bh   = u >> 5;
    int hch  = bh & 63;
    int pb   = hch*16 + half*8;

    const u64* wrp  = (const u64*)g_wre  + pb;
    const u64* wip  = (const u64*)g_wim  + pb;
    const u64* nwip = (const u64*)g_nwim + pb;
    u64 wre[8], wim[8], nwim[8], sre[8], sim[8];
    #pragma unroll
    for (int k = 0; k < 8; ++k) {
        wre[k] = wrp[k]; wim[k] = wip[k]; nwim[k] = nwip[k];
        sre[k] = 0ULL; sim[k] = 0ULL;
    }
    size_t gbase = (size_t)blockIdx.x * 64 * TT;

    for (int tile = 0; tile < TT/32; ++tile) {
        __syncthreads();
        #pragma unroll
        for (int it = 0; it < 16; ++it) {
            int idx = it*128 + tid;
            int uu = idx >> 5, lo = idx & 31;
            sh[uu*33 + lo] = g_buf0[gbase + (size_t)uu*TT + tile*32 + lo];
        }
        __syncthreads();
        #pragma unroll 4
        for (int l = 0; l < 32; ++l) {
            float hv = sh[ul*33 + l];
            u64 hh = pk2(hv, hv);
            #pragma unroll
            for (int k = 0; k < 8; ++k) {
                u64 t  = ffma2(nwim[k], sim[k], hh);
                u64 t2 = fmul2(wim[k],  sre[k]);
                sre[k] = ffma2(wre[k], sre[k], t);
                sim[k] = ffma2(wre[k], sim[k], t2);
            }
        }
    }
    /* dump local end-states to smem */
    int bh_loc = ul >> 5, c = ul & 31;
    #pragma unroll
    for (int k = 0; k < 8; ++k) {
        float a, bq;
        int n0 = (half*8 + k)*2;
        upk2(sre[k], a, bq); st_re[bh_loc][c][n0] = a; st_re[bh_loc][c][n0+1] = bq;
        upk2(sim[k], a, bq); st_im[bh_loc][c][n0] = a; st_im[bh_loc][c][n0+1] = bq;
    }
    __syncthreads();
    /* inter-chunk prefix scan in smem: 64 scan threads, one per (bh_loc, n) */
    if (tid < 64) {
        int bl = tid >> 5, n = tid & 31;
        int hc = (blockIdx.x*2 + bl) & 63;
        float wtr = g_wTre[hc*NN + n], wti = g_wTim[hc*NN + n];
        float Sre = 0.f, Sim = 0.f;
        #pragma unroll
        for (int cc = 0; cc < NCHK; ++cc) {
            float lre = st_re[bl][cc][n], lim = st_im[bl][cc][n];
            st_re[bl][cc][n] = Sre; st_im[bl][cc][n] = Sim;
            float nr = fmaf(wtr, Sre, fmaf(-wti, Sim, lre));
            float ni = fmaf(wtr, Sim, fmaf( wti, Sre, lim));
            Sre = nr; Sim = ni;
        }
    }
    __syncthreads();
    /* write init states to global (contiguous layout matches (bh,c,n)) */
    const float* fre = &st_re[0][0][0];
    const float* fim = &st_im[0][0][0];
    size_t ob = (size_t)blockIdx.x * 2048;
    for (int i = tid; i < 2048; i += 128) {
        g_stre[ob + i] = fre[i];
        g_stim[ob + i] = fim[i];
    }
}

/* ---------------- scanC: full scan with init states + output ---------------- */
__global__ void __launch_bounds__(128) scanC_kernel(const float* __restrict__ Dskip)
{
    __shared__ float sh [64*33];
    __shared__ float sho[64*33];
    int tid  = threadIdx.x;
    int ul   = tid >> 1, half = tid & 1;
    int u    = blockIdx.x*64 + ul;
    int bh   = u >> 5, c = u & 31;
    int hch  = bh & 63;
    int pb   = hch*16 + half*8;

    const u64* wrp  = (const u64*)g_wre  + pb;
    const u64* wip  = (const u64*)g_wim  + pb;
    const u64* nwip = (const u64*)g_nwim + pb;
    const u64* crp  = (const u64*)g_cre  + pb;
    const u64* cip  = (const u64*)g_cim  + pb;
    u64 wre[8], wim[8], nwim[8], cre[8], cim[8], sre[8], sim[8];
    int sb = (bh*NCHK + c)*NN + half*16;
    const u64* ire = (const u64*)(g_stre + sb);
    const u64* iim = (const u64*)(g_stim + sb);
    #pragma unroll
    for (int k = 0; k < 8; ++k) {
        wre[k] = wrp[k]; wim[k] = wip[k]; nwim[k] = nwip[k];
        cre[k] = crp[k]; cim[k] = cip[k];
        sre[k] = ire[k]; sim[k] = iim[k];
    }
    float dsk = Dskip[hch];
    size_t gbase = (size_t)blockIdx.x * 64 * TT;

    for (int tile = 0; tile < TT/32; ++tile) {
        __syncthreads();
        #pragma unroll
        for (int it = 0; it < 16; ++it) {
            int idx = it*128 + tid;
            int uu = idx >> 5, lo = idx & 31;
            sh[uu*33 + lo] = g_buf0[gbase + (size_t)uu*TT + tile*32 + lo];
        }
        __syncthreads();
        #pragma unroll 2
        for (int l = 0; l < 32; ++l) {
            float hv = sh[ul*33 + l];
            u64 hh = pk2(hv, hv);
            u64 ar = 0ULL, ai = 0ULL;
            #pragma unroll
            for (int k = 0; k < 8; ++k) {
                u64 t  = ffma2(nwim[k], sim[k], hh);
                u64 t2 = fmul2(wim[k],  sre[k]);
                sre[k] = ffma2(wre[k], sre[k], t);
                sim[k] = ffma2(wre[k], sim[k], t2);
                ar = ffma2(cre[k], sre[k], ar);
                ai = ffma2(cim[k], sim[k], ai);
            }
            float arl, arh, ail, aih;
            upk2(ar, arl, arh); upk2(ai, ail, aih);
            float p = (arl + arh) - (ail + aih);
            p += __shfl_xor_sync(0xffffffffu, p, 1);
            if (half == 0) sho[ul*33 + l] = fmaf(dsk, hv, 2.f*p);
        }
        __syncthreads();
        #pragma unroll
        for (int it = 0; it < 16; ++it) {
            int idx = it*128 + tid;
            int uu = idx >> 5, lo = idx & 31;
            g_buf1[gbase + (size_t)uu*TT + tile*32 + lo] = sho[uu*33 + lo];
        }
    }
}

/* ---------------- BN statistics (deterministic two-stage) ---------------- */
__global__ void __launch_bounds__(256) stats_kernel()
{
    int b = blockIdx.x, g = blockIdx.y;
    const float4* p = (const float4*)(g_buf0 + ((size_t)b*HH + g)*LL);
    float s = 0.f, s2 = 0.f;
    for (int i = threadIdx.x; i < LL/4; i += 256) {
        float4 v = p[i];
        s  += v.x + v.y + v.z + v.w;
        s2 += v.x*v.x + v.y*v.y + v.z*v.z + v.w*v.w;
    }
    __shared__ float r1[256], r2[256];
    r1[threadIdx.x] = s; r2[threadIdx.x] = s2;
    __syncthreads();
    for (int o = 128; o > 0; o >>= 1) {
        if (threadIdx.x < o) { r1[threadIdx.x] += r1[threadIdx.x+o]; r2[threadIdx.x] += r2[threadIdx.x+o]; }
        __syncthreads();
    }
    if (threadIdx.x == 0) {
        g_part[(g*BB + b)*2    ] = r1[0];
        g_part[(g*BB + b)*2 + 1] = r2[0];
    }
}

__global__ void fin_kernel()
{
    int g = threadIdx.x;
    if (g >= HH) return;
    float s = 0.f, s2 = 0.f;
    for (int b = 0; b < BB; ++b) { s += g_part[(g*BB+b)*2]; s2 += g_part[(g*BB+b)*2 + 1]; }
    float inv = 1.f / (float)(BB*LL);
    float m   = s * inv;
    float var = fmaf(s2, inv, -m*m);
    g_mean[g] = m;
    g_rstd[g] = rsqrtf(var + 1e-5f);
}

/* ---------------- fused BN + FiLM + PReLU + residual ---------------- */
__global__ void __launch_bounds__(256) final_kernel(const float* __restrict__ x,
        const float* __restrict__ res_w, const float* __restrict__ pa2, float* __restrict__ out)
{
    int idx = blockIdx.x*256 + threadIdx.x;
    int row = idx >> 12;
    int b = row >> 6, g = row & 63;
    float m  = g_mean[g], r = g_rstd[g];
    float ga = g_gb[b*2*HH + g], be = g_gb[b*2*HH + HH + g];
    float rw = res_w[g], aa = pa2[0];
    float4 y  = ((const float4*)g_buf0)[idx];
    float4 xv = ((const float4*)x)[idx];
    float4 o; float v;
    v = (y.x - m)*r; v = fmaf(ga, v, be); v = (v >= 0.f) ? v : aa*v; o.x = fmaf(rw, xv.x, v);
    v = (y.y - m)*r; v = fmaf(ga, v, be); v = (v >= 0.f) ? v : aa*v; o.y = fmaf(rw, xv.y, v);
    v = (y.z - m)*r; v = fmaf(ga, v, be); v = (v >= 0.f) ? v : aa*v; o.z = fmaf(rw, xv.z, v);
    v = (y.w - m)*r; v = fmaf(ga, v, be); v = (v >= 0.f) ? v : aa*v; o.w = fmaf(rw, xv.w, v);
    ((float4*)out)[idx] = o;
}

extern "C" void kernel_launch(void* const* d_in, const int* in_sizes, int n_in,
                              void* d_out, int out_size)
{
    const float* x        = (const float*)d_in[0];
    const float* cond     = (const float*)d_in[1];
    const float* linear_w = (const float*)d_in[2];
    const float* linear_b = (const float*)d_in[3];
    const float* prelu1_a = (const float*)d_in[4];
    const float* log_dt   = (const float*)d_in[5];
    const float* log_A_r  = (const float*)d_in[6];
    const float* A_imag   = (const float*)d_in[7];
    const float* C_re     = (const float*)d_in[8];
    const float* C_im     = (const float*)d_in[9];
    const float* Dskip    = (const float*)d_in[10];
    const float* out_w    = (const float*)d_in[11];
    const float* out_b    = (const float*)d_in[12];
    const float* film_w   = (const float*)d_in[13];
    const float* film_b   = (const float*)d_in[14];
    const float* prelu2_a = (const float*)d_in[15];
    const float* res_w    = (const float*)d_in[16];
    float* out = (float*)d_out;

    prep_kernel<<<32, 128>>>(log_dt, log_A_r, A_imag, C_re, C_im, cond, film_w, film_b);
    gemm64p_kernel<0><<<dim3(LL/256, BB), 256>>>(x, linear_w, linear_b, prelu1_a);
    scanA_kernel<<<NSEQ*NCHK/64, 128>>>();
    scanC_kernel<<<NSEQ*NCHK/64, 128>>>(Dskip);
    gemm64p_kernel<1><<<dim3(LL/256, BB), 256>>>(x, out_w, out_b, prelu1_a);
    stats_kernel<<<dim3(BB, HH), 256>>>();
    fin_kernel<<<1, 64>>>();
    final_kernel<<<NTOT/4/256, 256>>>(x, res_w, prelu2_a, out);
}